// round 4
// baseline (speedup 1.0000x reference)
#include <cuda_runtime.h>
#include <math.h>

#define NT 64
#define NH 2048
#define NI 1408
#define NE 32
#define NK 4
#define NPAIR (NT * NK)

// ---- scratch (device globals: no allocation allowed) ----
__device__ int   d_expert_count[NE];
__device__ int   d_expert_start[NE];
__device__ int   d_pair_token[NPAIR];      // pair -> token
__device__ int   d_pair_idx[NT * NK];      // (token,k) -> pair
__device__ float d_topk_w[NT * NK];        // routing weights
__device__ float d_mixed[NPAIR * NI];      // silu(gate)*up per pair
__device__ float d_pair_out[NPAIR * NH];   // down-projected per pair

// ============================================================
// Kernel 1: routing. One block, one thread per token.
// ============================================================
__global__ void route_kernel(const float* __restrict__ logits) {
    __shared__ int s_count[NE];
    __shared__ int s_start[NE];
    __shared__ int s_slot[NE];
    const int t = threadIdx.x;

    if (t < NE) { s_count[t] = 0; s_slot[t] = 0; }
    __syncthreads();

    float v[NE];
#pragma unroll
    for (int e = 0; e < NE; e++) v[e] = logits[t * NE + e];

    int ids[NK];
    float vals[NK];
#pragma unroll
    for (int k = 0; k < NK; k++) {
        int best = 0;
        float bv = -1e30f;
#pragma unroll
        for (int e = 0; e < NE; e++) {
            if (v[e] > bv) { bv = v[e]; best = e; }  // strict > : lowest index on tie
        }
        ids[k] = best;
        vals[k] = bv;
        v[best] = -1e30f;
    }

    // softmax over the top-k values (vals[0] is the max)
    float m = vals[0];
    float w[NK];
    float s = 0.f;
#pragma unroll
    for (int k = 0; k < NK; k++) { w[k] = expf(vals[k] - m); s += w[k]; }
    float inv = 1.f / s;
#pragma unroll
    for (int k = 0; k < NK; k++) d_topk_w[t * NK + k] = w[k] * inv;

    // count per expert
#pragma unroll
    for (int k = 0; k < NK; k++) atomicAdd(&s_count[ids[k]], 1);
    __syncthreads();

    if (t == 0) {
        int off = 0;
        for (int e = 0; e < NE; e++) { s_start[e] = off; off += s_count[e]; }
    }
    __syncthreads();

    // assign slots
#pragma unroll
    for (int k = 0; k < NK; k++) {
        int slot = atomicAdd(&s_slot[ids[k]], 1);
        int p = s_start[ids[k]] + slot;
        d_pair_token[p] = t;
        d_pair_idx[t * NK + k] = p;
    }
    if (t < NE) {
        d_expert_count[t] = s_count[t];
        d_expert_start[t] = s_start[t];
    }
}

// ============================================================
// Kernel 2: gate/up matvecs + SiLU gating.
// grid = (NI/8, NE), block = 256. One warp per inter row.
// Streams each weight row ONCE per 8-token chunk (nT<=8 common).
// ============================================================
__global__ void __launch_bounds__(256) gateup_kernel(
    const float* __restrict__ x,
    const float* __restrict__ w_gate,
    const float* __restrict__ w_up)
{
    const int e = blockIdx.y;
    const int nT = d_expert_count[e];
    if (nT == 0) return;
    const int start = d_expert_start[e];
    const int warp = threadIdx.x >> 5;
    const int lane = threadIdx.x & 31;
    const int i = blockIdx.x * 8 + warp;  // inter row

    const float4* __restrict__ wg = (const float4*)(w_gate + ((size_t)e * NI + i) * NH);
    const float4* __restrict__ wu = (const float4*)(w_up   + ((size_t)e * NI + i) * NH);

    for (int t0 = 0; t0 < nT; t0 += 8) {
        const float4* xp[8];
#pragma unroll
        for (int j = 0; j < 8; j++) {
            int idx = (t0 + j < nT) ? (t0 + j) : 0;  // pad with token 0 (discarded)
            xp[j] = (const float4*)(x + (size_t)d_pair_token[start + idx] * NH);
        }
        float ag[8], au[8];
#pragma unroll
        for (int j = 0; j < 8; j++) { ag[j] = 0.f; au[j] = 0.f; }

        for (int k = lane; k < NH / 4; k += 32) {
            const float4 a = __ldcs(&wg[k]);   // streaming: keep L1 for x
            const float4 b = __ldcs(&wu[k]);
#pragma unroll
            for (int j = 0; j < 8; j++) {
                const float4 xv = __ldg(&xp[j][k]);
                ag[j] = fmaf(a.x, xv.x, fmaf(a.y, xv.y, fmaf(a.z, xv.z, fmaf(a.w, xv.w, ag[j]))));
                au[j] = fmaf(b.x, xv.x, fmaf(b.y, xv.y, fmaf(b.z, xv.z, fmaf(b.w, xv.w, au[j]))));
            }
        }

#pragma unroll
        for (int j = 0; j < 8; j++) {
            float g = ag[j], u = au[j];
#pragma unroll
            for (int o = 16; o > 0; o >>= 1) {
                g += __shfl_down_sync(0xFFFFFFFFu, g, o);
                u += __shfl_down_sync(0xFFFFFFFFu, u, o);
            }
            if (lane == 0 && (t0 + j) < nT) {
                float sg = g / (1.f + expf(-g));   // silu
                d_mixed[(size_t)(start + t0 + j) * NI + i] = sg * u;
            }
        }
    }
}

// ============================================================
// Kernel 3: down projection per pair.
// grid = (NH/8, NE), block = 256. One warp per hidden row.
// ============================================================
__global__ void __launch_bounds__(256) down_kernel(const float* __restrict__ w_down)
{
    const int e = blockIdx.y;
    const int nT = d_expert_count[e];
    if (nT == 0) return;
    const int start = d_expert_start[e];
    const int warp = threadIdx.x >> 5;
    const int lane = threadIdx.x & 31;
    const int h = blockIdx.x * 8 + warp;

    const float4* __restrict__ wd = (const float4*)(w_down + ((size_t)e * NH + h) * NI);

    for (int t0 = 0; t0 < nT; t0 += 8) {
        const float4* mp[8];
#pragma unroll
        for (int j = 0; j < 8; j++) {
            int idx = (t0 + j < nT) ? (t0 + j) : 0;
            mp[j] = (const float4*)(d_mixed + (size_t)(start + idx) * NI);
        }
        float acc[8];
#pragma unroll
        for (int j = 0; j < 8; j++) acc[j] = 0.f;

        for (int k = lane; k < NI / 4; k += 32) {   // 352/32 = 11 iters
            const float4 a = __ldcs(&wd[k]);
#pragma unroll
            for (int j = 0; j < 8; j++) {
                const float4 mv = __ldg(&mp[j][k]);
                acc[j] = fmaf(a.x, mv.x, fmaf(a.y, mv.y, fmaf(a.z, mv.z, fmaf(a.w, mv.w, acc[j]))));
            }
        }

#pragma unroll
        for (int j = 0; j < 8; j++) {
            float s = acc[j];
#pragma unroll
            for (int o = 16; o > 0; o >>= 1)
                s += __shfl_down_sync(0xFFFFFFFFu, s, o);
            if (lane == 0 && (t0 + j) < nT)
                d_pair_out[(size_t)(start + t0 + j) * NH + h] = s;
        }
    }
}

// ============================================================
// Kernel 4: weighted combine of the 4 routed pair outputs.
// ============================================================
__global__ void combine_kernel(float* __restrict__ out)
{
    const int idx = blockIdx.x * blockDim.x + threadIdx.x;  // [0, NT*NH)
    const int t = idx / NH;
    const int h = idx - t * NH;
    float s = 0.f;
#pragma unroll
    for (int k = 0; k < NK; k++) {
        const int p = d_pair_idx[t * NK + k];
        s = fmaf(d_topk_w[t * NK + k], d_pair_out[(size_t)p * NH + h], s);
    }
    out[idx] = s;
}

// ============================================================
extern "C" void kernel_launch(void* const* d_in, const int* in_sizes, int n_in,
                              void* d_out, int out_size)
{
    const float* x      = (const float*)d_in[0];
    const float* logits = (const float*)d_in[1];
    const float* wg     = (const float*)d_in[2];
    const float* wu     = (const float*)d_in[3];
    const float* wd     = (const float*)d_in[4];
    float* out = (float*)d_out;

    route_kernel<<<1, NT>>>(logits);
    gateup_kernel<<<dim3(NI / 8, NE), 256>>>(x, wg, wu);
    down_kernel<<<dim3(NH / 8, NE), 256>>>(wd);
    combine_kernel<<<(NT * NH) / 256, 256>>>(out);
}

// round 5
// speedup vs baseline: 1.1688x; 1.1688x over previous
#include <cuda_runtime.h>
#include <math.h>

#define NT 64
#define NH 2048
#define NI 1408
#define NE 32
#define NK 4
#define NPAIR (NT * NK)

// ---- scratch (device globals: no allocation allowed) ----
__device__ int   d_expert_count[NE];
__device__ int   d_expert_start[NE];
__device__ int   d_pair_token[NPAIR];            // pair -> token
__device__ int   d_pair_idx[NT * NK];            // (token,k) -> pair
__device__ float d_topk_w[NT * NK];              // routing weights
__device__ float d_xg[(NPAIR + 2) * NH];         // gathered x rows, pair-ordered (+pad)
__device__ float d_mixed[(NPAIR + 2) * NI];      // silu(gate)*up per pair (+pad)
__device__ float d_pair_out[NPAIR * NH];         // down-projected per pair

// ---- packed f32x2 helpers (FFMA2 path: PTX-only per sm_103a) ----
__device__ __forceinline__ unsigned long long pk2(float lo, float hi) {
    unsigned long long r;
    asm("mov.b64 %0, {%1, %2};" : "=l"(r) : "f"(lo), "f"(hi));
    return r;
}
__device__ __forceinline__ void upk2(unsigned long long v, float& lo, float& hi) {
    asm("mov.b64 {%0, %1}, %2;" : "=f"(lo), "=f"(hi) : "l"(v));
}
__device__ __forceinline__ unsigned long long fma2(unsigned long long a,
                                                   unsigned long long b,
                                                   unsigned long long c) {
    unsigned long long d;
    asm("fma.rn.f32x2 %0, %1, %2, %3;" : "=l"(d) : "l"(a), "l"(b), "l"(c));
    return d;
}
__device__ __forceinline__ unsigned long long add2(unsigned long long a,
                                                   unsigned long long b) {
    unsigned long long d;
    asm("add.rn.f32x2 %0, %1, %2;" : "=l"(d) : "l"(a), "l"(b));
    return d;
}

// ============================================================
// Kernel 1: routing. One block, one thread per token.
// ============================================================
__global__ void route_kernel(const float* __restrict__ logits) {
    __shared__ int s_count[NE];
    __shared__ int s_start[NE];
    __shared__ int s_slot[NE];
    const int t = threadIdx.x;

    if (t < NE) { s_count[t] = 0; s_slot[t] = 0; }
    __syncthreads();

    float v[NE];
#pragma unroll
    for (int e = 0; e < NE; e++) v[e] = logits[t * NE + e];

    int ids[NK];
    float vals[NK];
#pragma unroll
    for (int k = 0; k < NK; k++) {
        int best = 0;
        float bv = -1e30f;
#pragma unroll
        for (int e = 0; e < NE; e++) {
            if (v[e] > bv) { bv = v[e]; best = e; }  // strict > : lowest index wins ties
        }
        ids[k] = best;
        vals[k] = bv;
        v[best] = -1e30f;
    }

    float m = vals[0];
    float w[NK];
    float s = 0.f;
#pragma unroll
    for (int k = 0; k < NK; k++) { w[k] = expf(vals[k] - m); s += w[k]; }
    float inv = 1.f / s;
#pragma unroll
    for (int k = 0; k < NK; k++) d_topk_w[t * NK + k] = w[k] * inv;

#pragma unroll
    for (int k = 0; k < NK; k++) atomicAdd(&s_count[ids[k]], 1);
    __syncthreads();

    if (t == 0) {
        int off = 0;
        for (int e = 0; e < NE; e++) { s_start[e] = off; off += s_count[e]; }
    }
    __syncthreads();

#pragma unroll
    for (int k = 0; k < NK; k++) {
        int slot = atomicAdd(&s_slot[ids[k]], 1);
        int p = s_start[ids[k]] + slot;
        d_pair_token[p] = t;
        d_pair_idx[t * NK + k] = p;
    }
    if (t < NE) {
        d_expert_count[t] = s_count[t];
        d_expert_start[t] = s_start[t];
    }
}

// ============================================================
// Kernel 1b: gather x rows into pair order (L2-resident, 2MB).
// ============================================================
__global__ void gather_kernel(const float* __restrict__ x) {
    const int p = blockIdx.x;
    const int t = d_pair_token[p];
    const float4* __restrict__ src = (const float4*)(x + (size_t)t * NH);
    float4* __restrict__ dst = (float4*)(d_xg + (size_t)p * NH);
    for (int k = threadIdx.x; k < NH / 4; k += blockDim.x) dst[k] = src[k];
}

// ============================================================
// Kernel 2: gate/up matvecs + SiLU. One warp per inter row,
// TP token-PAIRS register-blocked via FFMA2, weights streamed once.
// ============================================================
template<int TP>
__device__ __forceinline__ void gateup_body(
    const int nT, const float* __restrict__ xg,
    const float* __restrict__ wg_row, const float* __restrict__ wu_row,
    float* __restrict__ mixed_out, const int lane)
{
    const float4* __restrict__ wg = (const float4*)wg_row;
    const float4* __restrict__ wu = (const float4*)wu_row;

    unsigned long long ag[TP], au[TP];
#pragma unroll
    for (int p = 0; p < TP; p++) { ag[p] = 0ull; au[p] = 0ull; }

#pragma unroll 2
    for (int k = lane; k < NH / 4; k += 32) {   // 16 iterations
        const float4 a = __ldcs(&wg[k]);        // streaming: weights read once
        const float4 b = __ldcs(&wu[k]);
        const unsigned long long a0 = pk2(a.x, a.x), a1 = pk2(a.y, a.y),
                                 a2 = pk2(a.z, a.z), a3 = pk2(a.w, a.w);
        const unsigned long long b0 = pk2(b.x, b.x), b1 = pk2(b.y, b.y),
                                 b2 = pk2(b.z, b.z), b3 = pk2(b.w, b.w);
#pragma unroll
        for (int p = 0; p < TP; p++) {
            const float4 xA = __ldg((const float4*)(xg + (size_t)(2 * p)     * NH) + k);
            const float4 xB = __ldg((const float4*)(xg + (size_t)(2 * p + 1) * NH) + k);
            const unsigned long long x0 = pk2(xA.x, xB.x), x1 = pk2(xA.y, xB.y),
                                     x2 = pk2(xA.z, xB.z), x3 = pk2(xA.w, xB.w);
            ag[p] = fma2(a0, x0, ag[p]); ag[p] = fma2(a1, x1, ag[p]);
            ag[p] = fma2(a2, x2, ag[p]); ag[p] = fma2(a3, x3, ag[p]);
            au[p] = fma2(b0, x0, au[p]); au[p] = fma2(b1, x1, au[p]);
            au[p] = fma2(b2, x2, au[p]); au[p] = fma2(b3, x3, au[p]);
        }
    }

#pragma unroll
    for (int p = 0; p < TP; p++) {
#pragma unroll
        for (int o = 16; o > 0; o >>= 1) {
            ag[p] = add2(ag[p], __shfl_down_sync(0xFFFFFFFFu, ag[p], o));
            au[p] = add2(au[p], __shfl_down_sync(0xFFFFFFFFu, au[p], o));
        }
        if (lane == 0) {
            float gA, gB, uA, uB;
            upk2(ag[p], gA, gB);
            upk2(au[p], uA, uB);
            const int tA = 2 * p, tB = 2 * p + 1;
            if (tA < nT) mixed_out[(size_t)tA * NI] = (gA / (1.f + expf(-gA))) * uA;
            if (tB < nT) mixed_out[(size_t)tB * NI] = (gB / (1.f + expf(-gB))) * uB;
        }
    }
}

__global__ void __launch_bounds__(256) gateup_kernel(
    const float* __restrict__ w_gate, const float* __restrict__ w_up)
{
    const int e = blockIdx.y;
    const int nT = d_expert_count[e];
    if (nT == 0) return;
    const int start = d_expert_start[e];
    const int warp = threadIdx.x >> 5;
    const int lane = threadIdx.x & 31;
    const int i = blockIdx.x * 8 + warp;

    const float* wgr = w_gate + ((size_t)e * NI + i) * NH;
    const float* wur = w_up   + ((size_t)e * NI + i) * NH;
    const float* xg  = d_xg   + (size_t)start * NH;
    float* mo        = d_mixed + (size_t)start * NI + i;

    if      (nT <= 2)  gateup_body<1>(nT, xg, wgr, wur, mo, lane);
    else if (nT <= 4)  gateup_body<2>(nT, xg, wgr, wur, mo, lane);
    else if (nT <= 6)  gateup_body<3>(nT, xg, wgr, wur, mo, lane);
    else if (nT <= 8)  gateup_body<4>(nT, xg, wgr, wur, mo, lane);
    else if (nT <= 12) gateup_body<6>(nT, xg, wgr, wur, mo, lane);
    else if (nT <= 16) gateup_body<8>(nT, xg, wgr, wur, mo, lane);
    else {
        for (int c = 0; c < nT; c += 16) {
            const int n = (nT - c < 16) ? (nT - c) : 16;
            gateup_body<8>(n, xg + (size_t)c * NH, wgr, wur, mo + (size_t)c * NI, lane);
        }
    }
}

// ============================================================
// Kernel 3: down projection. One warp per hidden row, same scheme.
// ============================================================
template<int TP>
__device__ __forceinline__ void down_body(
    const int nT, const float* __restrict__ mx,
    const float* __restrict__ wd_row, float* __restrict__ pout, const int lane)
{
    const float4* __restrict__ wd = (const float4*)wd_row;
    unsigned long long acc[TP];
#pragma unroll
    for (int p = 0; p < TP; p++) acc[p] = 0ull;

#pragma unroll 2
    for (int k = lane; k < NI / 4; k += 32) {   // 11 iterations
        const float4 a = __ldcs(&wd[k]);
        const unsigned long long a0 = pk2(a.x, a.x), a1 = pk2(a.y, a.y),
                                 a2 = pk2(a.z, a.z), a3 = pk2(a.w, a.w);
#pragma unroll
        for (int p = 0; p < TP; p++) {
            const float4 xA = __ldg((const float4*)(mx + (size_t)(2 * p)     * NI) + k);
            const float4 xB = __ldg((const float4*)(mx + (size_t)(2 * p + 1) * NI) + k);
            const unsigned long long x0 = pk2(xA.x, xB.x), x1 = pk2(xA.y, xB.y),
                                     x2 = pk2(xA.z, xB.z), x3 = pk2(xA.w, xB.w);
            acc[p] = fma2(a0, x0, acc[p]); acc[p] = fma2(a1, x1, acc[p]);
            acc[p] = fma2(a2, x2, acc[p]); acc[p] = fma2(a3, x3, acc[p]);
        }
    }

#pragma unroll
    for (int p = 0; p < TP; p++) {
#pragma unroll
        for (int o = 16; o > 0; o >>= 1)
            acc[p] = add2(acc[p], __shfl_down_sync(0xFFFFFFFFu, acc[p], o));
        if (lane == 0) {
            float sA, sB;
            upk2(acc[p], sA, sB);
            const int tA = 2 * p, tB = 2 * p + 1;
            if (tA < nT) pout[(size_t)tA * NH] = sA;
            if (tB < nT) pout[(size_t)tB * NH] = sB;
        }
    }
}

__global__ void __launch_bounds__(256) down_kernel(const float* __restrict__ w_down)
{
    const int e = blockIdx.y;
    const int nT = d_expert_count[e];
    if (nT == 0) return;
    const int start = d_expert_start[e];
    const int warp = threadIdx.x >> 5;
    const int lane = threadIdx.x & 31;
    const int h = blockIdx.x * 8 + warp;

    const float* wdr = w_down + ((size_t)e * NH + h) * NI;
    const float* mx  = d_mixed + (size_t)start * NI;
    float* po        = d_pair_out + (size_t)start * NH + h;

    if      (nT <= 2)  down_body<1>(nT, mx, wdr, po, lane);
    else if (nT <= 4)  down_body<2>(nT, mx, wdr, po, lane);
    else if (nT <= 6)  down_body<3>(nT, mx, wdr, po, lane);
    else if (nT <= 8)  down_body<4>(nT, mx, wdr, po, lane);
    else if (nT <= 12) down_body<6>(nT, mx, wdr, po, lane);
    else if (nT <= 16) down_body<8>(nT, mx, wdr, po, lane);
    else {
        for (int c = 0; c < nT; c += 16) {
            const int n = (nT - c < 16) ? (nT - c) : 16;
            down_body<8>(n, mx + (size_t)c * NI, wdr, po + (size_t)c * NH, lane);
        }
    }
}

// ============================================================
// Kernel 4: weighted combine of the 4 routed pair outputs.
// ============================================================
__global__ void combine_kernel(float* __restrict__ out)
{
    const int idx = blockIdx.x * blockDim.x + threadIdx.x;  // [0, NT*NH)
    const int t = idx / NH;
    const int h = idx - t * NH;
    float s = 0.f;
#pragma unroll
    for (int k = 0; k < NK; k++) {
        const int p = d_pair_idx[t * NK + k];
        s = fmaf(d_topk_w[t * NK + k], d_pair_out[(size_t)p * NH + h], s);
    }
    out[idx] = s;
}

// ============================================================
extern "C" void kernel_launch(void* const* d_in, const int* in_sizes, int n_in,
                              void* d_out, int out_size)
{
    const float* x      = (const float*)d_in[0];
    const float* logits = (const float*)d_in[1];
    const float* wg     = (const float*)d_in[2];
    const float* wu     = (const float*)d_in[3];
    const float* wd     = (const float*)d_in[4];
    float* out = (float*)d_out;

    route_kernel<<<1, NT>>>(logits);
    gather_kernel<<<NPAIR, 256>>>(x);
    gateup_kernel<<<dim3(NI / 8, NE), 256>>>(wg, wu);
    down_kernel<<<dim3(NH / 8, NE), 256>>>(wd);
    combine_kernel<<<(NT * NH) / 256, 256>>>(out);
}